// round 6
// baseline (speedup 1.0000x reference)
#include <cuda_runtime.h>
#include <cuda_fp16.h>
#include <cstdint>

#define L_SEQ  1024
#define DMODEL 1024
#define DINNER 2048
#define NH     32
#define HD     64
#define NST    64
#define CONVD  2176
#define DPROJ  4256

// ---------------- scratch (static device globals; no allocations) ----------------
__device__ __align__(128) float g_zx [2 * L_SEQ * DPROJ];
__device__ __align__(128) float g_x  [2 * L_SEQ * DINNER];
__device__ __align__(128) float g_dtx[2 * L_SEQ * DINNER];
__device__ __align__(128) float g_dA [2 * L_SEQ * NH];
__device__ __align__(128) float g_Bv [2 * L_SEQ * NST];
__device__ __align__(128) float g_Cv [2 * L_SEQ * NST];
__device__ __align__(128) float g_y  [2 * L_SEQ * DINNER];   // n-half 0 partial
__device__ __align__(128) float g_y2 [2 * L_SEQ * DINNER];   // n-half 1 partial
__device__ __align__(128) float g_ygn[2 * L_SEQ * DINNER];
__device__ __align__(128) float g_t  [2 * L_SEQ * DMODEL];

// ---------------- helpers ----------------
__device__ __forceinline__ float silu_f(float v) { return v / (1.f + expf(-v)); }
__device__ __forceinline__ float softplus_f(float v) { return v > 20.f ? v : log1pf(expf(v)); }

// packed fp32x2 ops (sm_103a FFMA2 path — PTX-only)
typedef unsigned long long u64t;
__device__ __forceinline__ u64t pk2(float v) {
    u64t r; asm("mov.b64 %0, {%1, %1};" : "=l"(r) : "f"(v)); return r;
}
__device__ __forceinline__ u64t fma2(u64t a, u64t b, u64t c) {
    u64t d; asm("fma.rn.f32x2 %0, %1, %2, %3;" : "=l"(d) : "l"(a), "l"(b), "l"(c)); return d;
}
__device__ __forceinline__ u64t mul2(u64t a, u64t b) {
    u64t d; asm("mul.rn.f32x2 %0, %1, %2;" : "=l"(d) : "l"(a), "l"(b)); return d;
}
__device__ __forceinline__ float hadd2(u64t a) {
    float lo, hi; asm("mov.b64 {%0, %1}, %2;" : "=f"(lo), "=f"(hi) : "l"(a)); return lo + hi;
}

// fp16 mma m16n8k16: D(f32) += A(f16) @ B(f16)^T
__device__ __forceinline__ void mma_f16(float* c, const uint32_t* a, const uint32_t* b) {
    asm volatile(
        "mma.sync.aligned.m16n8k16.row.col.f32.f16.f16.f32 "
        "{%0,%1,%2,%3},{%4,%5,%6,%7},{%8,%9},{%0,%1,%2,%3};"
        : "+f"(c[0]), "+f"(c[1]), "+f"(c[2]), "+f"(c[3])
        : "r"(a[0]), "r"(a[1]), "r"(a[2]), "r"(a[3]), "r"(b[0]), "r"(b[1]));
}

__device__ __forceinline__ uint2 f4_to_h4(float4 v) {
    __half2 lo = __floats2half2_rn(v.x, v.y);
    __half2 hi = __floats2half2_rn(v.z, v.w);
    uint2 r;
    r.x = *reinterpret_cast<uint32_t*>(&lo);
    r.y = *reinterpret_cast<uint32_t*>(&hi);
    return r;
}

// ---------------- fp16 GEMM: C[M,N] = A[M,K] @ W[N,K]^T ----------------
// BM=128, BN=128, BK=32, 256 threads (8 warps as 2x4), warp tile 64x32.
// Half smem tiles, row stride 40 halves (20 u32) -> conflict-free fragment LDS.
// Double-buffered; register-staged gmem loads; one sync per K-iter.
// flip_mode: 0 none; 2: flip A rows when blockIdx.z==1; 3: final fusion
//            (A = silu(concat(g_t fwd, flipped g_t bwd)), lda ignored).
#define HSTRIDE_U32 20                       // 40 halves per row
#define HBUF_U32 (128 * HSTRIDE_U32)         // one 128x32 tile in u32 units

__global__ __launch_bounds__(256) void gemm_h(
    const float* __restrict__ A, int lda, int flip_mode,
    const float* __restrict__ W0, const float* __restrict__ W1, int ldw,
    float* __restrict__ C, int ldc, int M, int N, int K,
    long strideA, long strideC)
{
    __shared__ uint32_t As[2 * HBUF_U32];
    __shared__ uint32_t Ws[2 * HBUF_U32];

    const int z = blockIdx.z;
    const float* Ap = A + (size_t)z * strideA;
    const float* W  = z ? W1 : W0;
    float* Cp = C + (size_t)z * strideC;
    const bool flipA = (flip_mode == 2 && z == 1);
    const bool finalA = (flip_mode == 3);

    const int tid  = threadIdx.x;
    const int warp = tid >> 5, lane = tid & 31;
    const int g = lane >> 2, tg = lane & 3;
    const int wm = warp >> 2, wn = warp & 3;      // 2 x 4 warp grid
    const int mblk = blockIdx.y * 128;
    const int nblk = blockIdx.x * 128;
    const int m0 = wm * 64, n0 = wn * 32;

    const int lm = tid >> 3;               // 0..31 base row
    const int lk = (tid & 7) << 2;         // k offset within 32 (floats)

    float4 ra[4], rw[4];

#define LOAD_TILE(kt_) do {                                                                \
        _Pragma("unroll")                                                                  \
        for (int i = 0; i < 4; i++) {                                                      \
            int gr = mblk + lm + i * 32;                                                   \
            if (finalA) {                                                                  \
                int j = (kt_) + lk;                                                        \
                float4 v = (j < DMODEL)                                                    \
                    ? *reinterpret_cast<const float4*>(g_t + (size_t)gr * DMODEL + j)      \
                    : *reinterpret_cast<const float4*>(                                    \
                          g_t + (size_t)(L_SEQ + (L_SEQ - 1 - gr)) * DMODEL + (j - DMODEL)); \
                v.x = silu_f(v.x); v.y = silu_f(v.y); v.z = silu_f(v.z); v.w = silu_f(v.w); \
                ra[i] = v;                                                                 \
            } else {                                                                       \
                int row = flipA ? (M - 1 - gr) : gr;                                       \
                ra[i] = *reinterpret_cast<const float4*>(Ap + (size_t)row * lda + (kt_) + lk); \
            }                                                                              \
            int gn = nblk + lm + i * 32;                                                   \
            rw[i] = (gn < N) ? *reinterpret_cast<const float4*>(W + (size_t)gn * ldw + (kt_) + lk) \
                             : make_float4(0.f, 0.f, 0.f, 0.f);                            \
        }                                                                                  \
    } while (0)

#define COMMIT_TILE(buf_) do {                                                             \
        _Pragma("unroll")                                                                  \
        for (int i = 0; i < 4; i++) {                                                      \
            int off = (buf_) * HBUF_U32 + (lm + i * 32) * HSTRIDE_U32 + (lk >> 1);         \
            *reinterpret_cast<uint2*>(&As[off]) = f4_to_h4(ra[i]);                         \
            *reinterpret_cast<uint2*>(&Ws[off]) = f4_to_h4(rw[i]);                         \
        }                                                                                  \
    } while (0)

    LOAD_TILE(0);
    COMMIT_TILE(0);
    __syncthreads();

    float acc[4][4][4];
#pragma unroll
    for (int i = 0; i < 4; i++)
#pragma unroll
        for (int j = 0; j < 4; j++)
#pragma unroll
            for (int r = 0; r < 4; r++) acc[i][j][r] = 0.f;

    int b = 0;
    for (int kt = 0; kt < K; kt += 32) {
        const bool more = (kt + 32 < K);
        if (more) LOAD_TILE(kt + 32);

        const uint32_t* Ab = &As[b * HBUF_U32];
        const uint32_t* Wb = &Ws[b * HBUF_U32];
#pragma unroll
        for (int ks = 0; ks < 2; ks++) {
            const int kk = ks * 8;            // u32 offset (16 halves)
            uint32_t a[4][4], bb[4][2];
#pragma unroll
            for (int mt = 0; mt < 4; mt++) {
                int row = m0 + mt * 16 + g;
                a[mt][0] = Ab[row * HSTRIDE_U32 + kk + tg];
                a[mt][1] = Ab[(row + 8) * HSTRIDE_U32 + kk + tg];
                a[mt][2] = Ab[row * HSTRIDE_U32 + kk + tg + 4];
                a[mt][3] = Ab[(row + 8) * HSTRIDE_U32 + kk + tg + 4];
            }
#pragma unroll
            for (int nt = 0; nt < 4; nt++) {
                int col = n0 + nt * 8 + g;
                bb[nt][0] = Wb[col * HSTRIDE_U32 + kk + tg];
                bb[nt][1] = Wb[col * HSTRIDE_U32 + kk + tg + 4];
            }
#pragma unroll
            for (int mt = 0; mt < 4; mt++)
#pragma unroll
                for (int nt = 0; nt < 4; nt++)
                    mma_f16(acc[mt][nt], a[mt], bb[nt]);
        }
        if (more) {
            COMMIT_TILE(b ^ 1);
            __syncthreads();
        }
        b ^= 1;
    }

    // epilogue
#pragma unroll
    for (int mt = 0; mt < 4; mt++) {
#pragma unroll
        for (int nt = 0; nt < 4; nt++) {
            int row = mblk + m0 + mt * 16 + g;
            int col = nblk + n0 + nt * 8 + 2 * tg;
            if (col < N) {
                Cp[(size_t)row * ldc + col]           = acc[mt][nt][0];
                Cp[(size_t)(row + 8) * ldc + col]     = acc[mt][nt][2];
            }
            if (col + 1 < N) {
                Cp[(size_t)row * ldc + col + 1]       = acc[mt][nt][1];
                Cp[(size_t)(row + 8) * ldc + col + 1] = acc[mt][nt][3];
            }
        }
    }
}

// ---------------- prep: causal dwconv + silu, dt softplus, dA, dtx ----------------
__global__ __launch_bounds__(256) void prep_kernel(
    const float* __restrict__ cw_f, const float* __restrict__ cb_f,
    const float* __restrict__ cw_b, const float* __restrict__ cb_b,
    const float* __restrict__ dtb_f, const float* __restrict__ dtb_b,
    const float* __restrict__ Alog_f, const float* __restrict__ Alog_b)
{
    const int l = blockIdx.x, dir = blockIdx.y, tid = threadIdx.x;
    const float* cw   = dir ? cw_b   : cw_f;
    const float* cb   = dir ? cb_b   : cb_f;
    const float* dtb  = dir ? dtb_b  : dtb_f;
    const float* Alog = dir ? Alog_b : Alog_f;

    const size_t base = (size_t)dir * L_SEQ + l;
    const float* zrow = g_zx + base * DPROJ;

    __shared__ float sdt[NH];
    if (tid < NH) {
        float dt = softplus_f(zrow[4224 + tid] + dtb[tid]);
        sdt[tid] = dt;
        g_dA[base * NH + tid] = expf(-expf(Alog[tid]) * dt);
    }
    __syncthreads();

    for (int c = tid; c < CONVD; c += 256) {
        float s = cb[c];
#pragma unroll
        for (int t = 0; t < 4; t++) {
            int lp = l - 3 + t;
            if (lp >= 0)
                s = fmaf(cw[c * 4 + t],
                         g_zx[((size_t)dir * L_SEQ + lp) * DPROJ + 2048 + c], s);
        }
        float v = silu_f(s);
        if (c < DINNER) {
            g_x[base * DINNER + c]   = v;
            g_dtx[base * DINNER + c] = sdt[c >> 6] * v;
        } else if (c < 2112) {
            g_Bv[base * NST + (c - 2048)] = v;
        } else {
            g_Cv[base * NST + (c - 2112)] = v;
        }
    }
}

// ---------------- sequential SSM scan (f32x2, n-split across blocks) ----------------
#define SCH 16

__global__ __launch_bounds__(256) void scan_kernel()
{
    const int ps = blockIdx.x & 1, ns = blockIdx.x >> 1;
    const int hh = blockIdx.y, dir = blockIdx.z;
    const int tid = threadIdx.x;
    const int pl = tid >> 3, q = tid & 7;

    __shared__ __align__(16) float sB[SCH][32], sC[SCH][32], sdt[SCH][32];
    __shared__ float sdA[SCH];

    u64t h0 = 0ull, h1 = 0ull;

    const size_t dbase = (size_t)dir * L_SEQ;
    const int pcol  = hh * HD + ps * 32;
    const int nbase = ns * 32;
    float* yout = ns ? g_y2 : g_y;

    for (int c0 = 0; c0 < L_SEQ; c0 += SCH) {
        if (tid < 128) {
            int s = tid >> 3, cc = (tid & 7) << 2;
            *reinterpret_cast<float4*>(&sB[s][cc]) =
                *reinterpret_cast<const float4*>(g_Bv + (dbase + c0 + s) * NST + nbase + cc);
            *reinterpret_cast<float4*>(&sdt[s][cc]) =
                *reinterpret_cast<const float4*>(g_dtx + (dbase + c0 + s) * DINNER + pcol + cc);
        } else {
            int t2 = tid - 128;
            int s = t2 >> 3, cc = (t2 & 7) << 2;
            *reinterpret_cast<float4*>(&sC[s][cc]) =
                *reinterpret_cast<const float4*>(g_Cv + (dbase + c0 + s) * NST + nbase + cc);
            if (t2 < SCH) sdA[t2] = g_dA[(dbase + c0 + t2) * NH + hh];
        }
        __syncthreads();

#pragma unroll
        for (int s = 0; s < SCH; s++) {
            const u64t dA2 = pk2(sdA[s]);
            const u64t dt2 = pk2(sdt[s][pl]);
            ulonglong2 b2 = *reinterpret_cast<const ulonglong2*>(&sB[s][q * 4]);
            ulonglong2 c2 = *reinterpret_cast<const ulonglong2*>(&sC[s][q * 4]);
            h0 = fma2(h0, dA2, mul2(dt2, b2.x));
            h1 = fma2(h1, dA2, mul2(dt2, b2.y));
            u64t acc = fma2(h1, c2.y, mul2(h0, c2.x));
            float a = hadd2(acc);
            a += __shfl_xor_sync(0xffffffffu, a, 1);
            a += __shfl_xor_sync(0xffffffffu, a, 2);
            a += __shfl_xor_sync(0xffffffffu, a, 4);
            if (q == 0)
                yout[(dbase + c0 + s) * DINNER + pcol + pl] = a;
        }
        __syncthreads();
    }
}

// ---------------- gate: (y0+y1) + D*x, *silu(z), rmsnorm, *norm_w (float4) ----------------
__global__ __launch_bounds__(256) void gate_kernel(
    const float* __restrict__ D_f, const float* __restrict__ D_b,
    const float* __restrict__ nw_f, const float* __restrict__ nw_b)
{
    const int l = blockIdx.x, dir = blockIdx.y, tid = threadIdx.x;
    const float* Dp = dir ? D_b : D_f;
    const float* nw = dir ? nw_b : nw_f;
    const size_t base = (size_t)dir * L_SEQ + l;

    const float4* y4  = reinterpret_cast<const float4*>(g_y  + base * DINNER);
    const float4* y24 = reinterpret_cast<const float4*>(g_y2 + base * DINNER);
    const float4* x4  = reinterpret_cast<const float4*>(g_x  + base * DINNER);
    const float4* z4  = reinterpret_cast<const float4*>(g_zx + base * DPROJ);
    float4* o4 = reinterpret_cast<float4*>(g_ygn + base * DINNER);

    float ss = 0.f;
#pragma unroll
    for (int it = 0; it < 2; it++) {
        int c4 = tid + it * 256;
        float dd = Dp[c4 >> 4];
        float4 a = y4[c4], b = y24[c4], x = x4[c4], z = z4[c4];
        float4 r;
        r.x = (a.x + b.x + dd * x.x) * silu_f(z.x);
        r.y = (a.y + b.y + dd * x.y) * silu_f(z.y);
        r.z = (a.z + b.z + dd * x.z) * silu_f(z.z);
        r.w = (a.w + b.w + dd * x.w) * silu_f(z.w);
        o4[c4] = r;
        ss += r.x * r.x + r.y * r.y + r.z * r.z + r.w * r.w;
    }
    __shared__ float red[8];
#pragma unroll
    for (int o = 16; o; o >>= 1) ss += __shfl_xor_sync(0xffffffffu, ss, o);
    if ((tid & 31) == 0) red[tid >> 5] = ss;
    __syncthreads();
    if (tid < 8) {
        float v = red[tid];
#pragma unroll
        for (int o = 4; o; o >>= 1) v += __shfl_xor_sync(0xffu, v, o);
        if (tid == 0) red[0] = v;
    }
    __syncthreads();
    const float scale = rsqrtf(red[0] * (1.f / DINNER) + 1e-5f);
    const float4* nw4 = reinterpret_cast<const float4*>(nw);
#pragma unroll
    for (int it = 0; it < 2; it++) {
        int c4 = tid + it * 256;
        float4 r = o4[c4], w = nw4[c4];
        r.x *= scale * w.x; r.y *= scale * w.y; r.z *= scale * w.z; r.w *= scale * w.w;
        o4[c4] = r;
    }
}

// ---------------- launch ----------------
extern "C" void kernel_launch(void* const* d_in, const int* in_sizes, int n_in,
                              void* d_out, int out_size)
{
    const float* u         = (const float*)d_in[0];
    const float* W_in_f    = (const float*)d_in[1];
    const float* W_in_b    = (const float*)d_in[2];
    const float* conv_w_f  = (const float*)d_in[3];
    const float* conv_b_f  = (const float*)d_in[4];
    const float* conv_w_b  = (const float*)d_in[5];
    const float* conv_b_b  = (const float*)d_in[6];
    const float* dt_bias_f = (const float*)d_in[7];
    const float* dt_bias_b = (const float*)d_in[8];
    const float* A_log_f   = (const float*)d_in[9];
    const float* A_log_b   = (const float*)d_in[10];
    const float* D_f       = (const float*)d_in[11];
    const float* D_b       = (const float*)d_in[12];
    const float* norm_w_f  = (const float*)d_in[13];
    const float* norm_w_b  = (const float*)d_in[14];
    const float* W_out_f   = (const float*)d_in[15];
    const float* W_out_b   = (const float*)d_in[16];
    const float* W_out     = (const float*)d_in[17];

    float *zx, *ygn, *tbuf;
    cudaGetSymbolAddress((void**)&zx,   g_zx);
    cudaGetSymbolAddress((void**)&ygn,  g_ygn);
    cudaGetSymbolAddress((void**)&tbuf, g_t);

    // 1) in_proj, both directions in one launch (z=dir; flip A rows when z==1)
    gemm_h<<<dim3((DPROJ + 127) / 128, L_SEQ / 128, 2), 256>>>(
        u, DMODEL, 2, W_in_f, W_in_b, DMODEL, zx, DPROJ,
        L_SEQ, DPROJ, DMODEL, 0, (long)L_SEQ * DPROJ);

    // 2) conv + silu + dt/dA/dtx
    prep_kernel<<<dim3(L_SEQ, 2), 256>>>(conv_w_f, conv_b_f, conv_w_b, conv_b_b,
                                         dt_bias_f, dt_bias_b, A_log_f, A_log_b);

    // 3) sequential scan (p-half x n-half x head x dir)
    scan_kernel<<<dim3(4, NH, 2), 256>>>();

    // 4) gate + rmsnorm
    gate_kernel<<<dim3(L_SEQ, 2), 256>>>(D_f, D_b, norm_w_f, norm_w_b);

    // 5) per-direction out projections, one launch (z selects weights)
    gemm_h<<<dim3(DMODEL / 128, L_SEQ / 128, 2), 256>>>(
        ygn, DINNER, 0, W_out_f, W_out_b, DINNER, tbuf, DMODEL,
        L_SEQ, DMODEL, DINNER, (long)L_SEQ * DINNER, (long)L_SEQ * DMODEL);

    // 6) final projection with fused silu(concat(fwd, flip(bwd))) A-staging
    gemm_h<<<dim3(DMODEL / 128, L_SEQ / 128, 1), 256>>>(
        nullptr, 0, 3, W_out, W_out, 2 * DMODEL, (float*)d_out, DMODEL,
        L_SEQ, DMODEL, 2 * DMODEL, 0, 0);
}

// round 8
// speedup vs baseline: 1.7198x; 1.7198x over previous
#include <cuda_runtime.h>
#include <cuda_fp16.h>
#include <cstdint>

#define L_SEQ  1024
#define DMODEL 1024
#define DINNER 2048
#define NH     32
#define HD     64
#define NST    64
#define CONVD  2176
#define DPROJ  4256

// ---------------- scratch (static device globals; no allocations) ----------------
__device__ __align__(128) float g_zx [2 * L_SEQ * DPROJ];
__device__ __align__(128) float g_x  [2 * L_SEQ * DINNER];
__device__ __align__(128) float g_dtx[2 * L_SEQ * DINNER];
__device__ __align__(128) float g_dA [2 * L_SEQ * NH];
__device__ __align__(128) float g_Bv [2 * L_SEQ * NST];
__device__ __align__(128) float g_Cv [2 * L_SEQ * NST];
__device__ __align__(128) float g_y  [2 * L_SEQ * DINNER];   // n-half 0 partial
__device__ __align__(128) float g_y2 [2 * L_SEQ * DINNER];   // n-half 1 partial
__device__ __align__(128) float g_ygn[2 * L_SEQ * DINNER];   // fp32 scratch (pre-norm)

// fp16 mirrors for GEMM inputs
__device__ __align__(128) __half g_hWin  [2 * DPROJ * DMODEL];
__device__ __align__(128) __half g_hWoutF[DMODEL * DINNER];
__device__ __align__(128) __half g_hWoutB[DMODEL * DINNER];
__device__ __align__(128) __half g_hWout [DMODEL * 2 * DMODEL];
__device__ __align__(128) __half g_hu    [L_SEQ * DMODEL];
__device__ __align__(128) __half g_hygn  [2 * L_SEQ * DINNER];
__device__ __align__(128) __half g_hG    [L_SEQ * 2 * DMODEL];

// ---------------- helpers ----------------
__device__ __forceinline__ float silu_f(float v) { return v / (1.f + expf(-v)); }
__device__ __forceinline__ float softplus_f(float v) { return v > 20.f ? v : log1pf(expf(v)); }

// packed fp32x2 ops (sm_103a FFMA2 path — PTX-only)
typedef unsigned long long u64t;
__device__ __forceinline__ u64t pk2(float v) {
    u64t r; asm("mov.b64 %0, {%1, %1};" : "=l"(r) : "f"(v)); return r;
}
__device__ __forceinline__ u64t fma2(u64t a, u64t b, u64t c) {
    u64t d; asm("fma.rn.f32x2 %0, %1, %2, %3;" : "=l"(d) : "l"(a), "l"(b), "l"(c)); return d;
}
__device__ __forceinline__ u64t mul2(u64t a, u64t b) {
    u64t d; asm("mul.rn.f32x2 %0, %1, %2;" : "=l"(d) : "l"(a), "l"(b)); return d;
}
__device__ __forceinline__ float hadd2(u64t a) {
    float lo, hi; asm("mov.b64 {%0, %1}, %2;" : "=f"(lo), "=f"(hi) : "l"(a)); return lo + hi;
}

__device__ __forceinline__ void mma_f16(float* c, const uint32_t* a, uint32_t b0, uint32_t b1) {
    asm volatile(
        "mma.sync.aligned.m16n8k16.row.col.f32.f16.f16.f32 "
        "{%0,%1,%2,%3},{%4,%5,%6,%7},{%8,%9},{%0,%1,%2,%3};"
        : "+f"(c[0]), "+f"(c[1]), "+f"(c[2]), "+f"(c[3])
        : "r"(a[0]), "r"(a[1]), "r"(a[2]), "r"(a[3]), "r"(b0), "r"(b1));
}

__device__ __forceinline__ uint2 f4_to_h4(float4 v) {
    __half2 lo = __floats2half2_rn(v.x, v.y);
    __half2 hi = __floats2half2_rn(v.z, v.w);
    uint2 r;
    r.x = *reinterpret_cast<uint32_t*>(&lo);
    r.y = *reinterpret_cast<uint32_t*>(&hi);
    return r;
}

__device__ __forceinline__ uint32_t smem_u32(const void* p) {
    uint32_t a;
    asm("{ .reg .u64 t; cvta.to.shared.u64 t, %1; cvt.u32.u64 %0, t; }" : "=r"(a) : "l"(p));
    return a;
}
__device__ __forceinline__ uint32_t swz64(uint32_t o) { return o ^ ((o >> 3) & 0x30); }

#define CP16(dst, src) \
    asm volatile("cp.async.cg.shared.global [%0], [%1], 16;" :: "r"(dst), "l"(src) : "memory")
#define CP_COMMIT() asm volatile("cp.async.commit_group;" ::: "memory")
#define CP_WAIT2()  asm volatile("cp.async.wait_group 2;" ::: "memory")

#define LDSM4(r, addr) \
    asm volatile("ldmatrix.sync.aligned.m8n8.x4.shared.b16 {%0,%1,%2,%3}, [%4];" \
                 : "=r"((r)[0]), "=r"((r)[1]), "=r"((r)[2]), "=r"((r)[3]) : "r"(addr))

// ---------------- fp16 GEMM, 4-stage cp.async + ldmatrix ----------------
// C[M,N] = A[M,K] @ W[N,K]^T ; A/W fp16 in gmem (64B rows staged with SW64 swizzle).
// BM=128, BN=128, BK=32, 256 threads (8 warps 2x4), warp tile 64x32, m16n8k16.
// epi: 0 = fp32 store to C; 1 = silu->half into g_hG (fwd z=0 / flipped z=1).
#define STG_BYTES 16384              // A(8KB) + B(8KB) per stage
#define GEMM_SMEM (4 * STG_BYTES)

__global__ __launch_bounds__(256, 2) void gemm_hp(
    const __half* __restrict__ A, int lda, int flip_z1,
    const __half* __restrict__ W0, const __half* __restrict__ W1, int ldw,
    float* __restrict__ C, int ldc, int M, int N, int K,
    long strideA, long strideC, int epi)
{
    extern __shared__ __align__(128) char smem[];
    const uint32_t sbase = smem_u32(smem);

    const int z = blockIdx.z;
    const __half* Ap = A + (size_t)z * strideA;
    const __half* W  = z ? W1 : W0;
    float* Cp = C + (size_t)z * strideC;
    const bool flipA = (flip_z1 && z == 1);

    const int tid  = threadIdx.x;
    const int warp = tid >> 5, lane = tid & 31;
    const int g = lane >> 2, tg = lane & 3;
    const int wm = warp >> 2, wn = warp & 3;
    const int mblk = blockIdx.y * 128;
    const int nblk = blockIdx.x * 128;
    const int m0 = wm * 64, n0 = wn * 32;

    // precomputed swizzled fragment offsets
    uint32_t offA[4][2], offB[2][2];
    {
        int mrow = (lane & 7) + ((lane >> 3) & 1) * 8;
        int kcA  = lane >> 4;
#pragma unroll
        for (int mt = 0; mt < 4; mt++)
#pragma unroll
            for (int ks = 0; ks < 2; ks++)
                offA[mt][ks] = swz64((m0 + mt * 16 + mrow) * 64 + ks * 32 + kcA * 16);
        int nrow = (lane & 7) + (lane >> 4) * 8;
        int kcB  = (lane >> 3) & 1;
#pragma unroll
        for (int p = 0; p < 2; p++)
#pragma unroll
            for (int ks = 0; ks < 2; ks++)
                offB[p][ks] = swz64((n0 + p * 16 + nrow) * 64 + ks * 32 + kcB * 16) + 8192;
    }

    // staging coordinates: 2 chunks of 16B per matrix per thread
    const int srow0 = tid >> 2,          spos0 = tid & 3;
    const int srow1 = (tid + 256) >> 2,  spos1 = (tid + 256) & 3;
    const uint32_t sd0 = swz64(srow0 * 64 + spos0 * 16);
    const uint32_t sd1 = swz64(srow1 * 64 + spos1 * 16);

    const int T = K / 32;

#define ISSUE(t_) do {                                                         \
        int kt = (t_) * 32;                                                    \
        uint32_t sb = sbase + ((t_) & 3) * STG_BYTES;                          \
        {   int gr = mblk + srow0; int rA = flipA ? (M - 1 - gr) : gr;         \
            CP16(sb + sd0, Ap + (size_t)rA * lda + kt + spos0 * 8);            \
            int gn = nblk + srow0; if (gn >= N) gn = N - 1;                    \
            CP16(sb + 8192 + sd0, W + (size_t)gn * ldw + kt + spos0 * 8); }    \
        {   int gr = mblk + srow1; int rA = flipA ? (M - 1 - gr) : gr;         \
            CP16(sb + sd1, Ap + (size_t)rA * lda + kt + spos1 * 8);            \
            int gn = nblk + srow1; if (gn >= N) gn = N - 1;                    \
            CP16(sb + 8192 + sd1, W + (size_t)gn * ldw + kt + spos1 * 8); }    \
    } while (0)

    ISSUE(0); CP_COMMIT();
    ISSUE(1); CP_COMMIT();
    ISSUE(2); CP_COMMIT();

    float acc[4][4][4];
#pragma unroll
    for (int i = 0; i < 4; i++)
#pragma unroll
        for (int j = 0; j < 4; j++)
#pragma unroll
            for (int r = 0; r < 4; r++) acc[i][j][r] = 0.f;

    for (int t = 0; t < T; t++) {
        CP_WAIT2();
        __syncthreads();
        const uint32_t sb = sbase + (t & 3) * STG_BYTES;

#pragma unroll
        for (int ks = 0; ks < 2; ks++) {
            uint32_t a[4][4], b[2][4];
#pragma unroll
            for (int mt = 0; mt < 4; mt++) LDSM4(a[mt], sb + offA[mt][ks]);
#pragma unroll
            for (int p = 0; p < 2; p++)    LDSM4(b[p], sb + offB[p][ks]);
#pragma unroll
            for (int mt = 0; mt < 4; mt++)
#pragma unroll
                for (int nt = 0; nt < 4; nt++)
                    mma_f16(acc[mt][nt], a[mt], b[nt >> 1][(nt & 1) * 2],
                            b[nt >> 1][(nt & 1) * 2 + 1]);
        }

        if (t + 3 < T) ISSUE(t + 3);
        CP_COMMIT();
    }

    // epilogue
    if (epi == 0) {
#pragma unroll
        for (int mt = 0; mt < 4; mt++) {
#pragma unroll
            for (int nt = 0; nt < 4; nt++) {
                int row = mblk + m0 + mt * 16 + g;
                int col = nblk + n0 + nt * 8 + 2 * tg;
                if (col < N) {
                    Cp[(size_t)row * ldc + col]           = acc[mt][nt][0];
                    Cp[(size_t)(row + 8) * ldc + col]     = acc[mt][nt][2];
                }
                if (col + 1 < N) {
                    Cp[(size_t)row * ldc + col + 1]       = acc[mt][nt][1];
                    Cp[(size_t)(row + 8) * ldc + col + 1] = acc[mt][nt][3];
                }
            }
        }
    } else {
        // out_proj: write silu(acc) as fp16 into g_hG (concat + bwd flip fused)
#pragma unroll
        for (int mt = 0; mt < 4; mt++) {
#pragma unroll
            for (int nt = 0; nt < 4; nt++) {
                int row = mblk + m0 + mt * 16 + g;
                int col = nblk + n0 + nt * 8 + 2 * tg;
                __half2 h0 = __floats2half2_rn(silu_f(acc[mt][nt][0]), silu_f(acc[mt][nt][1]));
                __half2 h1 = __floats2half2_rn(silu_f(acc[mt][nt][2]), silu_f(acc[mt][nt][3]));
                if (z == 0) {
                    *reinterpret_cast<__half2*>(&g_hG[(size_t)row * 2 * DMODEL + col])       = h0;
                    *reinterpret_cast<__half2*>(&g_hG[(size_t)(row + 8) * 2 * DMODEL + col]) = h1;
                } else {
                    *reinterpret_cast<__half2*>(&g_hG[(size_t)(L_SEQ - 1 - row) * 2 * DMODEL + DMODEL + col]) = h0;
                    *reinterpret_cast<__half2*>(&g_hG[(size_t)(L_SEQ - 9 - row) * 2 * DMODEL + DMODEL + col]) = h1;
                }
            }
        }
    }
}

// ---------------- fp32 -> fp16 conversion (weights + u), grid-stride ----------------
__global__ __launch_bounds__(256) void cvt6_kernel(
    const float* __restrict__ s0, const float* __restrict__ s1,
    const float* __restrict__ s2, const float* __restrict__ s3,
    const float* __restrict__ s4, const float* __restrict__ s5)
{
    const int stride = gridDim.x * blockDim.x;
    const int gid = blockIdx.x * blockDim.x + threadIdx.x;
    const float* srcs[6] = {s0, s1, s2, s3, s4, s5};
    __half* dsts[6] = {g_hWin, g_hWin + DPROJ * DMODEL, g_hWoutF, g_hWoutB, g_hWout, g_hu};
    const int cnts[6] = {DPROJ * DMODEL / 4, DPROJ * DMODEL / 4, DMODEL * DINNER / 4,
                         DMODEL * DINNER / 4, DMODEL * 2 * DMODEL / 4, L_SEQ * DMODEL / 4};
#pragma unroll
    for (int seg = 0; seg < 6; seg++) {
        const float4* src = reinterpret_cast<const float4*>(srcs[seg]);
        uint2* dst = reinterpret_cast<uint2*>(dsts[seg]);
        for (int i = gid; i < cnts[seg]; i += stride)
            dst[i] = f4_to_h4(src[i]);
    }
}

// ---------------- prep: causal dwconv + silu, dt softplus, dA, dtx ----------------
__global__ __launch_bounds__(256) void prep_kernel(
    const float* __restrict__ cw_f, const float* __restrict__ cb_f,
    const float* __restrict__ cw_b, const float* __restrict__ cb_b,
    const float* __restrict__ dtb_f, const float* __restrict__ dtb_b,
    const float* __restrict__ Alog_f, const float* __restrict__ Alog_b)
{
    const int l = blockIdx.x, dir = blockIdx.y, tid = threadIdx.x;
    const float* cw   = dir ? cw_b   : cw_f;
    const float* cb   = dir ? cb_b   : cb_f;
    const float* dtb  = dir ? dtb_b  : dtb_f;
    const float* Alog = dir ? Alog_b : Alog_f;

    const size_t base = (size_t)dir * L_SEQ + l;
    const float* zrow = g_zx + base * DPROJ;

    __shared__ float sdt[NH];
    if (tid < NH) {
        float dt = softplus_f(zrow[4224 + tid] + dtb[tid]);
        sdt[tid] = dt;
        g_dA[base * NH + tid] = expf(-expf(Alog[tid]) * dt);
    }
    __syncthreads();

    for (int c = tid; c < CONVD; c += 256) {
        float s = cb[c];
#pragma unroll
        for (int t = 0; t < 4; t++) {
            int lp = l - 3 + t;
            if (lp >= 0)
                s = fmaf(cw[c * 4 + t],
                         g_zx[((size_t)dir * L_SEQ + lp) * DPROJ + 2048 + c], s);
        }
        float v = silu_f(s);
        if (c < DINNER) {
            g_x[base * DINNER + c]   = v;
            g_dtx[base * DINNER + c] = sdt[c >> 6] * v;
        } else if (c < 2112) {
            g_Bv[base * NST + (c - 2048)] = v;
        } else {
            g_Cv[base * NST + (c - 2112)] = v;
        }
    }
}

// ---------------- sequential SSM scan (f32x2, n-split across blocks) ----------------
#define SCH 16

__global__ __launch_bounds__(256) void scan_kernel()
{
    const int ps = blockIdx.x & 1, ns = blockIdx.x >> 1;
    const int hh = blockIdx.y, dir = blockIdx.z;
    const int tid = threadIdx.x;
    const int pl = tid >> 3, q = tid & 7;

    __shared__ __align__(16) float sB[SCH][32], sC[SCH][32], sdt[SCH][32];
    __shared__ float sdA[SCH];

    u64t h0 = 0ull, h1 = 0ull;

    const size_t dbase = (size_t)dir * L_SEQ;
    const int pcol  = hh * HD + ps * 32;
    const int nbase = ns * 32;
    float* yout = ns ? g_y2 : g_y;

    for (int c0 = 0; c0 < L_SEQ; c0 += SCH) {
        if (tid < 128) {
            int s = tid >> 3, cc = (tid & 7) << 2;
            *reinterpret_cast<float4*>(&sB[s][cc]) =
                *reinterpret_cast<const float4*>(g_Bv + (dbase + c0 + s) * NST + nbase + cc);
            *reinterpret_cast<float4*>(&sdt[s][cc]) =
                *reinterpret_cast<const float4*>(g_dtx + (dbase + c0 + s) * DINNER + pcol + cc);
        } else {
            int t2 = tid - 128;
            int s = t2 >> 3, cc = (t2 & 7) << 2;
            *reinterpret_cast<float4*>(&sC[s][cc]) =
                *reinterpret_cast<const float4*>(g_Cv + (dbase + c0 + s) * NST + nbase + cc);
            if (t2 < SCH) sdA[t2] = g_dA[(dbase + c0 + t2) * NH + hh];
        }
        __syncthreads();

#pragma unroll
        for (int s = 0; s < SCH; s++) {
            const u64t dA2 = pk2(sdA[s]);
            const u64t dt2 = pk2(sdt[s][pl]);
            ulonglong2 b2 = *reinterpret_cast<const ulonglong2*>(&sB[s][q * 4]);
            ulonglong2 c2 = *reinterpret_cast<const ulonglong2*>(&sC[s][q * 4]);
            h0 = fma2(h0, dA2, mul2(dt2, b2.x));
            h1 = fma2(h1, dA2, mul2(dt2, b2.y));
            u64t acc = fma2(h1, c2.y, mul2(h0, c2.x));
            float a = hadd2(acc);
            a += __shfl_xor_sync(0xffffffffu, a, 1);
            a += __shfl_xor_sync(0xffffffffu, a, 2);
            a += __shfl_xor_sync(0xffffffffu, a, 4);
            if (q == 0)
                yout[(dbase + c0 + s) * DINNER + pcol + pl] = a;
        }
        __syncthreads();
    }
}

// ---------------- gate: (y0+y1) + D*x, *silu(z), rmsnorm, *norm_w -> fp16 ----------------
__global__ __launch_bounds__(256) void gate_kernel(
    const float* __restrict__ D_f, const float* __restrict__ D_b,
    const float* __restrict__ nw_f, const float* __restrict__ nw_b)
{
    const int l = blockIdx.x, dir = blockIdx.y, tid = threadIdx.x;
    const float* Dp = dir ? D_b : D_f;
    const float* nw = dir ? nw_b : nw_f;
    const size_t base = (size_t)dir * L_SEQ + l;

    const float4* y4  = reinterpret_cast<const float4*>(g_y  + base * DINNER);
    const float4* y24 = reinterpret_cast<const float4*>(g_y2 + base * DINNER);
    const float4* x4  = reinterpret_cast<const float4*>(g_x  + base * DINNER);
    const float4* z4  = reinterpret_cast<const float4*>(g_zx + base * DPROJ);
    float4* o4 = reinterpret_cast<float4*>(g_ygn + base * DINNER);
    uint2* h4 = reinterpret_cast<uint2*>(g_hygn + base * DINNER);

    float ss = 0.f;
#pragma unroll
    for (int it = 0; it < 2; it++) {
        int c4 = tid + it * 256;
        float dd = Dp[c4 >> 4];
        float4 a = y4[c4], b = y24[c4], x = x4[c4], z = z4[c4];
        float4 r;
        r.x = (a.x + b.x + dd * x.x) * silu_f(z.x);
        r.y = (a.y + b.y + dd * x.y) * silu_f(z.y);
        r.z = (a.z + b.z + dd * x.z) * silu_f(z.z);
        r.w = (a.w + b.w + dd * x.w) * silu_f(z.w);
        o4[c4] = r;
        ss += r.x * r.x + r.y * r.y + r.z * r.z + r.w * r.w;
    }
    __shared__ float red[8];
#pragma unroll
    for (int o = 16; o; o >>= 1) ss += __shfl_xor_sync(0xffffffffu, ss, o);
    if ((tid & 31) == 0) red[tid >> 5] = ss;
    __syncthreads();
    if (tid < 8) {
        float v = red[tid];
#pragma unroll
        for (int o = 4; o; o >>= 1) v += __shfl_xor_sync(0xffu, v, o);
        if (tid == 0) red[0] = v;
    }
    __syncthreads();
    const float scale = rsqrtf(red[0] * (1.f / DINNER) + 1e-5f);
    const float4* nw4 = reinterpret_cast<const float4*>(nw);
#pragma unroll
    for (int it = 0; it < 2; it++) {
        int c4 = tid + it * 256;
        float4 r = o4[c4], w = nw4[c4];
        r.x *= scale * w.x; r.y *= scale * w.y; r.z *= scale * w.z; r.w *= scale * w.w;
        h4[c4] = f4_to_h4(r);
    }
}

// ---------------- launch ----------------
extern "C" void kernel_launch(void* const* d_in, const int* in_sizes, int n_in,
                              void* d_out, int out_size)
{
    const float* u         = (const float*)d_in[0];
    const float* W_in_f    = (const float*)d_in[1];
    const float* W_in_b    = (const float*)d_in[2];
    const float* conv_w_f  = (const float*)d_in[3];
    const float* conv_b_f  = (const float*)d_in[4];
    const float* conv_w_b  = (const float*)d_in[5];
    const float* conv_b_b  = (const float*)d_in[6];
    const float* dt_bias_f = (const float*)d_in[7];
    const float* dt_bias_b = (const float*)d_in[8];
    const float* A_log_f   = (const float*)d_in[9];
    const float* A_log_b   = (const float*)d_in[10];
    const float* D_f       = (const float*)d_in[11];
    const float* D_b       = (const float*)d_in[12];
    const float* norm_w_f  = (const float*)d_in[13];
    const float* norm_w_b  = (const float*)d_in[14];
    const float* W_out_f   = (const float*)d_in[15];
    const float* W_out_b   = (const float*)d_in[16];
    const float* W_out     = (const float*)d_in[17];

    static int attr_done = 0;
    if (!attr_done) {
        cudaFuncSetAttribute(gemm_hp, cudaFuncAttributeMaxDynamicSharedMemorySize, GEMM_SMEM);
        attr_done = 1;
    }

    float *zx;
    __half *hWin, *hWoutF, *hWoutB, *hWout, *hu, *hygn, *hG;
    cudaGetSymbolAddress((void**)&zx,     g_zx);
    cudaGetSymbolAddress((void**)&hWin,   g_hWin);
    cudaGetSymbolAddress((void**)&hWoutF, g_hWoutF);
    cudaGetSymbolAddress((void**)&hWoutB, g_hWoutB);
    cudaGetSymbolAddress((void**)&hWout,  g_hWout);
    cudaGetSymbolAddress((void**)&hu,     g_hu);
    cudaGetSymbolAddress((void**)&hygn,   g_hygn);
    cudaGetSymbolAddress((void**)&hG,     g_hG);

    // 0) fp32 -> fp16 conversions (weights + u)
    cvt6_kernel<<<1024, 256>>>(W_in_f, W_in_b, W_out_f, W_out_b, W_out, u);

    // 1) in_proj, both directions (z=dir; flip A rows when z==1)
    gemm_hp<<<dim3((DPROJ + 127) / 128, L_SEQ / 128, 2), 256, GEMM_SMEM>>>(
        hu, DMODEL, 1, hWin, hWin + (size_t)DPROJ * DMODEL, DMODEL, zx, DPROJ,
        L_SEQ, DPROJ, DMODEL, 0, (long)L_SEQ * DPROJ, 0);

    // 2) conv + silu + dt/dA/dtx
    prep_kernel<<<dim3(L_SEQ, 2), 256>>>(conv_w_f, conv_b_f, conv_w_b, conv_b_b,
                                         dt_bias_f, dt_bias_b, A_log_f, A_log_b);

    // 3) sequential scan (p-half x n-half x head x dir)
    scan_kernel<<<dim3(4, NH, 2), 256>>>();

    // 4) gate + rmsnorm -> fp16 ygn
    gate_kernel<<<dim3(L_SEQ, 2), 256>>>(D_f, D_b, norm_w_f, norm_w_b);

    // 5) out projections, epi=1 fuses silu + concat + flip into g_hG
    gemm_hp<<<dim3(DMODEL / 128, L_SEQ / 128, 2), 256, GEMM_SMEM>>>(
        hygn, DINNER, 0, hWoutF, hWoutB, DINNER, zx /*unused*/, DMODEL,
        L_SEQ, DMODEL, DINNER, (long)L_SEQ * DINNER, 0, 1);

    // 6) final projection
    gemm_hp<<<dim3(DMODEL / 128, L_SEQ / 128, 1), 256, GEMM_SMEM>>>(
        hG, 2 * DMODEL, 0, hWout, hWout, 2 * DMODEL, (float*)d_out, DMODEL,
        L_SEQ, DMODEL, 2 * DMODEL, 0, 0, 0);
}